// round 4
// baseline (speedup 1.0000x reference)
#include <cuda_runtime.h>
#include <math.h>
#include <stdint.h>

#define B_ 8
#define N_ 2048
#define W_ 64
#define R_ 4
#define EPS_ 1e-8f
#define TI_ 128

typedef unsigned long long u64;

// ---------------- device scratch ----------------
__device__ float g_fwd [B_*R_*N_];
__device__ float g_bwdp[B_*16*R_*N_];
__device__ float g_cw  [B_*R_*N_];
__device__ float g_gate[B_*R_*3];
__device__ float g_P   [B_*R_];
__device__ float g_S   [B_*R_];

// ---------------- f32x2 helpers ----------------
__device__ __forceinline__ u64 pk(float a, float b){
    u64 r; asm("mov.b64 %0,{%1,%2};" : "=l"(r) : "f"(a), "f"(b)); return r;
}
__device__ __forceinline__ void upk(u64 x, float& a, float& b){
    asm("mov.b64 {%0,%1},%2;" : "=f"(a), "=f"(b) : "l"(x));
}
__device__ __forceinline__ u64 add2(u64 a, u64 b){
    u64 d; asm("add.rn.f32x2 %0,%1,%2;" : "=l"(d) : "l"(a), "l"(b)); return d;
}
__device__ __forceinline__ u64 sub2(u64 a, u64 b){
    u64 d; asm("sub.rn.f32x2 %0,%1,%2;" : "=l"(d) : "l"(a), "l"(b)); return d;
}
__device__ __forceinline__ u64 mul2(u64 a, u64 b){
    u64 d; asm("mul.rn.f32x2 %0,%1,%2;" : "=l"(d) : "l"(a), "l"(b)); return d;
}
__device__ __forceinline__ u64 fma2(u64 a, u64 b, u64 c){
    u64 d; asm("fma.rn.f32x2 %0,%1,%2,%3;" : "=l"(d) : "l"(a), "l"(b), "l"(c)); return d;
}

// ---------------- mbarrier / bulk-copy helpers ----------------
__device__ __forceinline__ uint32_t smem_u32(const void* p){
    return (uint32_t)__cvta_generic_to_shared(p);
}
__device__ __forceinline__ void mbar_init(uint32_t a, uint32_t cnt){
    asm volatile("mbarrier.init.shared.b64 [%0], %1;" :: "r"(a), "r"(cnt) : "memory");
}
__device__ __forceinline__ void mbar_expect(uint32_t a, uint32_t bytes){
    asm volatile("mbarrier.arrive.expect_tx.shared.b64 _, [%0], %1;" :: "r"(a), "r"(bytes) : "memory");
}
__device__ __forceinline__ void bulk_g2s(uint32_t dst, const void* src, uint32_t bytes, uint32_t bar){
    asm volatile("cp.async.bulk.shared::cluster.global.mbarrier::complete_tx::bytes [%0], [%1], %2, [%3];"
                 :: "r"(dst), "l"(src), "r"(bytes), "r"(bar) : "memory");
}
__device__ __forceinline__ void mbar_wait(uint32_t a, uint32_t ph){
    asm volatile("{\n\t.reg .pred P;\n\tWL%=:\n\tmbarrier.try_wait.parity.shared.b64 P, [%0], %1;\n\t@P bra WD%=;\n\tbra WL%=;\n\tWD%=:\n\t}"
                 :: "r"(a), "r"(ph) : "memory");
}

// ================= k_pre: scalars + content + softmax, one block per (b,r) =================
__global__ void __launch_bounds__(512)
k_pre(const float* __restrict__ mem, const float* __restrict__ controls,
      const float* __restrict__ ww, const float* __restrict__ p,
      const float* __restrict__ prw, float* __restrict__ out)
{
    int br = blockIdx.x, b = br >> 2, r = br & 3;
    int tid = threadIdx.x, warp = tid >> 5, lane = tid & 31;
    __shared__ __align__(16) float s_key[64];
    __shared__ float s_sc[2048];
    __shared__ u64   s_r1[16];
    __shared__ float s_r2[16];
    __shared__ float s_bk[2];

    float accP = 0.f, accS = 0.f;
    for (int k = tid; k < N_; k += 512) {
        float t = prw[br*N_ + k];
        accP += p [b*N_ + k]*t;
        accS += ww[b*N_ + k]*t;
    }
    float kq = 0.f;
    if (tid < 64) { float kv = controls[b*272 + r*64 + tid]; s_key[tid] = kv; kq = kv*kv; }

    u64 pp = pk(accP, accS);
    #pragma unroll
    for (int m = 16; m; m >>= 1) {
        pp  = add2(pp, __shfl_xor_sync(~0u, pp, m));
        kq += __shfl_xor_sync(~0u, kq, m);
    }
    if (lane == 0) { s_r1[warp] = pp; s_r2[warp] = kq; }
    __syncthreads();
    if (tid == 0) {
        float P = 0.f, S = 0.f, K = 0.f;
        #pragma unroll
        for (int i = 0; i < 16; ++i) { float x, y; upk(s_r1[i], x, y); P += x; S += y; K += s_r2[i]; }
        g_P[br] = P; g_S[br] = S;
        float x = controls[b*272 + 256 + r];
        float beta = 1.f + ((x > 15.f) ? x : log1pf(__expf(x)));
        float e0 = controls[b*272 + 260 + r*3 + 0];
        float e1 = controls[b*272 + 260 + r*3 + 1];
        float e2 = controls[b*272 + 260 + r*3 + 2];
        float mm = fmaxf(e0, fmaxf(e1, e2));
        float x0 = __expf(e0-mm), x1 = __expf(e1-mm), x2 = __expf(e2-mm);
        float inv = 1.f/(x0+x1+x2);
        g_gate[br*3+0] = x0*inv; g_gate[br*3+1] = x1*inv; g_gate[br*3+2] = x2*inv;
        s_bk[0] = beta; s_bk[1] = sqrtf(K);
    }
    if (tid < 64) out[br*64 + tid] = 0.f;
    __syncthreads();

    // content scores: 2 rows per warp iter (16 lanes per row)
    float beta = s_bk[0], kn = s_bk[1];
    int half = lane >> 4, h = lane & 15;
    for (int it = 0; it < 64; ++it) {
        int n = warp*128 + it*2 + half;
        float4 m4 = *(const float4*)(mem + ((size_t)(b*N_ + n))*W_ + h*4);
        float4 k4 = *(const float4*)(s_key + h*4);
        float dot = m4.x*k4.x + m4.y*k4.y + m4.z*k4.z + m4.w*k4.w;
        float nrm = m4.x*m4.x + m4.y*m4.y + m4.z*m4.z + m4.w*m4.w;
        u64 pr = pk(dot, nrm);
        #pragma unroll
        for (int m = 8; m; m >>= 1) pr = add2(pr, __shfl_xor_sync(~0u, pr, m));
        if (h == 0) { float d, q; upk(pr, d, q); s_sc[n] = beta*d/(kn*sqrtf(q) + EPS_); }
    }
    __syncthreads();

    // softmax over 2048
    float v[4]; float mx = -1e30f;
    #pragma unroll
    for (int k = 0; k < 4; ++k) { v[k] = s_sc[tid + k*512]; mx = fmaxf(mx, v[k]); }
    #pragma unroll
    for (int m = 16; m; m >>= 1) mx = fmaxf(mx, __shfl_xor_sync(~0u, mx, m));
    if (lane == 0) s_r2[warp] = mx;
    __syncthreads();
    if (tid == 0) { float m2 = s_r2[0]; for (int i = 1; i < 16; ++i) m2 = fmaxf(m2, s_r2[i]); s_bk[0] = m2; }
    __syncthreads();
    mx = s_bk[0];
    float s = 0.f;
    #pragma unroll
    for (int k = 0; k < 4; ++k) { v[k] = __expf(v[k]-mx); s += v[k]; }
    #pragma unroll
    for (int m = 16; m; m >>= 1) s += __shfl_xor_sync(~0u, s, m);
    __syncthreads();
    if (lane == 0) s_r2[warp] = s;
    __syncthreads();
    if (tid == 0) { float t = 0.f; for (int i = 0; i < 16; ++i) t += s_r2[i]; s_bk[1] = 1.f/t; }
    __syncthreads();
    float inv = s_bk[1];
    #pragma unroll
    for (int k = 0; k < 4; ++k) g_cw[br*N_ + tid + k*512] = v[k]*inv;
}

// ================= k_stream: single pass over L with bulk-async double buffer =================
#define STAGE_BYTES 65536         // 8 rows x 2048 x 4B
#define SMEM_DYN    166416
#define SP(sel,row,w) s_part[(((sel)*128 + (row))*16) + (w)]

__global__ void __launch_bounds__(512)
k_stream(const float* __restrict__ L, const float* __restrict__ ww,
         const float* __restrict__ prw)
{
    extern __shared__ __align__(16) unsigned char dsm[];
    float* stg0   = (float*)(dsm);
    float* stg1   = (float*)(dsm + 65536);
    u64*   s_part = (u64*)  (dsm + 131072);   // [2][128][16]
    float* s_a    = (float*)(dsm + 163840);
    float* s_pi   = (float*)(dsm + 164352);   // [4][128]
    u64*   s_bar  = (u64*)  (dsm + 166400);

    int b = blockIdx.x >> 4, tile = blockIdx.x & 15, i0 = tile*TI_;
    int tid = threadIdx.x, w = tid >> 5, lane = tid & 31;
    int half = lane >> 4, h = lane & 15;

    if (tid < TI_) s_a[tid] = 1.f - ww[b*N_ + i0 + tid];
    if (tid < R_*TI_) s_pi[tid] = prw[(b*4 + (tid >> 7))*N_ + i0 + (tid & 127)];

    uint32_t bar0 = smem_u32(s_bar), bar1 = bar0 + 8;
    uint32_t st0 = smem_u32(stg0), st1 = smem_u32(stg1);
    if (tid == 0) { mbar_init(bar0, 1); mbar_init(bar1, 1); }
    __syncthreads();

    const char* src = (const char*)(L + ((size_t)(b*N_ + i0))*N_);
    if (tid == 0) {
        mbar_expect(bar0, STAGE_BYTES); bulk_g2s(st0, src,                 STAGE_BYTES, bar0);
        mbar_expect(bar1, STAGE_BYTES); bulk_g2s(st1, src + STAGE_BYTES,   STAGE_BYTES, bar1);
    }

    int jA = w*128 + h*4, jB = jA + 64;
    u64 pj[4][4];
    #pragma unroll
    for (int r = 0; r < 4; ++r) {
        float4 A  = *(const float4*)(prw + (b*4+r)*N_ + jA);
        float4 Bv = *(const float4*)(prw + (b*4+r)*N_ + jB);
        pj[r][0] = pk(A.x, A.y);  pj[r][1] = pk(A.z, A.w);
        pj[r][2] = pk(Bv.x, Bv.y); pj[r][3] = pk(Bv.z, Bv.w);
    }
    float4 wA = *(const float4*)(ww + b*N_ + jA);
    float4 wB = *(const float4*)(ww + b*N_ + jB);
    u64 wj[4] = { pk(wA.x,wA.y), pk(wA.z,wA.w), pk(wB.x,wB.y), pk(wB.z,wB.w) };

    u64 bw[4][4];
    #pragma unroll
    for (int r = 0; r < 4; ++r)
        #pragma unroll
        for (int k = 0; k < 4; ++k) bw[r][k] = 0ull;

    uint32_t ph0 = 0, ph1 = 0;
    for (int g = 0; g < 16; ++g) {
        if (g & 1) { mbar_wait(bar1, ph1); ph1 ^= 1; }
        else       { mbar_wait(bar0, ph0); ph0 ^= 1; }
        const float* stg = (g & 1) ? stg1 : stg0;

        #pragma unroll
        for (int it = 0; it < 4; ++it) {
            int lrow = it*2 + half;
            int row  = g*8 + lrow;
            float4 A  = *(const float4*)(stg + lrow*2048 + jA);
            float4 Bv = *(const float4*)(stg + lrow*2048 + jB);
            u64 l0 = pk(A.x,A.y), l1 = pk(A.z,A.w), l2 = pk(Bv.x,Bv.y), l3 = pk(Bv.z,Bv.w);
            float a = s_a[row];
            u64 av = pk(a, a);
            u64 c0 = mul2(sub2(av, wj[0]), l0);
            u64 c1 = mul2(sub2(av, wj[1]), l1);
            u64 c2 = mul2(sub2(av, wj[2]), l2);
            u64 c3 = mul2(sub2(av, wj[3]), l3);

            float f[4];
            #pragma unroll
            for (int r = 0; r < 4; ++r) {
                u64 t = mul2(c0, pj[r][0]);
                t = fma2(c1, pj[r][1], t);
                t = fma2(c2, pj[r][2], t);
                t = fma2(c3, pj[r][3], t);
                float x, y; upk(t, x, y); f[r] = x + y;
                float pi = s_pi[r*128 + row];
                u64 pr = pk(pi, pi);
                bw[r][0] = fma2(c0, pr, bw[r][0]);
                bw[r][1] = fma2(c1, pr, bw[r][1]);
                bw[r][2] = fma2(c2, pr, bw[r][2]);
                bw[r][3] = fma2(c3, pr, bw[r][3]);
            }
            u64 f01 = pk(f[0], f[1]), f23 = pk(f[2], f[3]);
            #pragma unroll
            for (int m = 8; m; m >>= 1) {
                f01 = add2(f01, __shfl_xor_sync(~0u, f01, m));
                f23 = add2(f23, __shfl_xor_sync(~0u, f23, m));
            }
            if (h == 0) { SP(0, row, w) = f01; SP(1, row, w) = f23; }
        }
        __syncthreads();
        if (tid == 0 && g + 2 < 16) {
            uint32_t bb = (g & 1) ? bar1 : bar0;
            uint32_t st = (g & 1) ? st1  : st0;
            mbar_expect(bb, STAGE_BYTES);
            bulk_g2s(st, src + (size_t)(g+2)*STAGE_BYTES, STAGE_BYTES, bb);
        }
    }

    // bwd: combine halves, flush per-tile partial
    #pragma unroll
    for (int r = 0; r < 4; ++r)
        #pragma unroll
        for (int k = 0; k < 4; ++k)
            bw[r][k] = add2(bw[r][k], __shfl_xor_sync(~0u, bw[r][k], 16));
    if (half == 0) {
        #pragma unroll
        for (int r = 0; r < 4; ++r) {
            float* dst = g_bwdp + ((size_t)((b*16 + tile)*4 + r))*N_;
            ulonglong2 v0; v0.x = bw[r][0]; v0.y = bw[r][1];
            ulonglong2 v1; v1.x = bw[r][2]; v1.y = bw[r][3];
            *(ulonglong2*)(dst + jA) = v0;
            *(ulonglong2*)(dst + jB) = v1;
        }
    }

    // fold fwd partials: one (row,r) per thread
    {
        int row = tid >> 2, r = tid & 3;
        const float* sp = (const float*)&SP(r >> 1, row, 0);
        float s = 0.f;
        #pragma unroll
        for (int w2 = 0; w2 < 16; ++w2) s += sp[w2*2 + (r & 1)];
        g_fwd[(b*4 + r)*N_ + i0 + row] = s;
    }
}

// ================= k_post: rw assembly + read vector, one block per (b, chunk) =================
__global__ void __launch_bounds__(256)
k_post(const float* __restrict__ mem, const float* __restrict__ L,
       const float* __restrict__ ww, const float* __restrict__ p,
       const float* __restrict__ prw, float* __restrict__ out)
{
    int b = blockIdx.x >> 3, c = blockIdx.x & 7;
    int n0 = c*256;
    int tid = threadIdx.x, warp = tid >> 5, lane = tid & 31;
    __shared__ float s_rw[4][256];
    __shared__ float s_acc[8][4][64];

    int n = n0 + tid;
    float wn  = ww[b*N_ + n];
    float pn  = p [b*N_ + n];
    float Lnn = L[((size_t)(b*N_ + n))*N_ + n];
    float ell = (1.f - 2.f*wn)*Lnn + wn*pn;
    #pragma unroll
    for (int r = 0; r < 4; ++r) {
        int br = b*4 + r;
        float bp = 0.f;
        #pragma unroll
        for (int t = 0; t < 16; ++t) bp += g_bwdp[((size_t)((b*16 + t)*4 + r))*N_ + n];
        float prn = prw[br*N_ + n];
        float fwd = g_fwd[br*N_ + n] + wn*g_P[br] - ell*prn;
        float bwd = bp + pn*g_S[br] - ell*prn;
        s_rw[r][tid] = g_gate[br*3]*fwd + g_gate[br*3+1]*bwd + g_gate[br*3+2]*g_cw[br*N_ + n];
    }
    __syncthreads();

    float2 acc[4];
    #pragma unroll
    for (int r = 0; r < 4; ++r) { acc[r].x = 0.f; acc[r].y = 0.f; }
    for (int k = 0; k < 32; ++k) {
        int nl = warp*32 + k;
        float2 m = *(const float2*)(mem + ((size_t)(b*N_ + n0 + nl))*W_ + lane*2);
        #pragma unroll
        for (int r = 0; r < 4; ++r) {
            float rv = s_rw[r][nl];
            acc[r].x += m.x*rv;
            acc[r].y += m.y*rv;
        }
    }
    #pragma unroll
    for (int r = 0; r < 4; ++r) {
        s_acc[warp][r][lane*2]   = acc[r].x;
        s_acc[warp][r][lane*2+1] = acc[r].y;
    }
    __syncthreads();
    {
        int r = tid >> 6, wd = tid & 63;
        float s = 0.f;
        #pragma unroll
        for (int k = 0; k < 8; ++k) s += s_acc[k][r][wd];
        atomicAdd(&out[(b*4 + r)*64 + wd], s);
    }
}

// ================= launcher =================
extern "C" void kernel_launch(void* const* d_in, const int* in_sizes, int n_in,
                              void* d_out, int out_size)
{
    const float* mem      = (const float*)d_in[0];
    const float* controls = (const float*)d_in[1];
    const float* ww       = (const float*)d_in[2];
    const float* L        = (const float*)d_in[3];
    const float* p        = (const float*)d_in[4];
    const float* prw      = (const float*)d_in[5];
    float* out = (float*)d_out;

    cudaFuncSetAttribute(k_stream, cudaFuncAttributeMaxDynamicSharedMemorySize, SMEM_DYN);

    k_pre   <<<B_*R_, 512>>>(mem, controls, ww, p, prw, out);
    k_stream<<<B_*16, 512, SMEM_DYN>>>(L, ww, prw);
    k_post  <<<B_*8, 256>>>(mem, L, ww, p, prw, out);
}

// round 5
// speedup vs baseline: 1.4286x; 1.4286x over previous
#include <cuda_runtime.h>
#include <math.h>
#include <stdint.h>

#define B_ 8
#define N_ 2048
#define W_ 64
#define R_ 4
#define EPS_ 1e-8f
#define TI_ 128

typedef unsigned long long u64;

// ---------------- device scratch ----------------
__device__ float g_fwd [B_*R_*N_];
__device__ float g_bwdp[B_*16*R_*N_];
__device__ float g_cw  [B_*R_*N_];
__device__ float g_gate[B_*R_*3];
__device__ float g_P   [B_*R_];
__device__ float g_S   [B_*R_];

// ---------------- f32x2 helpers ----------------
__device__ __forceinline__ u64 pk(float a, float b){
    u64 r; asm("mov.b64 %0,{%1,%2};" : "=l"(r) : "f"(a), "f"(b)); return r;
}
__device__ __forceinline__ void upk(u64 x, float& a, float& b){
    asm("mov.b64 {%0,%1},%2;" : "=f"(a), "=f"(b) : "l"(x));
}
__device__ __forceinline__ u64 add2(u64 a, u64 b){
    u64 d; asm("add.rn.f32x2 %0,%1,%2;" : "=l"(d) : "l"(a), "l"(b)); return d;
}
__device__ __forceinline__ u64 sub2(u64 a, u64 b){
    u64 d; asm("sub.rn.f32x2 %0,%1,%2;" : "=l"(d) : "l"(a), "l"(b)); return d;
}
__device__ __forceinline__ u64 mul2(u64 a, u64 b){
    u64 d; asm("mul.rn.f32x2 %0,%1,%2;" : "=l"(d) : "l"(a), "l"(b)); return d;
}
__device__ __forceinline__ u64 fma2(u64 a, u64 b, u64 c){
    u64 d; asm("fma.rn.f32x2 %0,%1,%2,%3;" : "=l"(d) : "l"(a), "l"(b), "l"(c)); return d;
}

// ---------------- mbarrier / bulk-copy helpers ----------------
__device__ __forceinline__ uint32_t smem_u32(const void* p){
    return (uint32_t)__cvta_generic_to_shared(p);
}
__device__ __forceinline__ void mbar_init(uint32_t a, uint32_t cnt){
    asm volatile("mbarrier.init.shared.b64 [%0], %1;" :: "r"(a), "r"(cnt) : "memory");
}
__device__ __forceinline__ void mbar_expect(uint32_t a, uint32_t bytes){
    asm volatile("mbarrier.arrive.expect_tx.shared.b64 _, [%0], %1;" :: "r"(a), "r"(bytes) : "memory");
}
__device__ __forceinline__ void bulk_g2s(uint32_t dst, const void* src, uint32_t bytes, uint32_t bar){
    asm volatile("cp.async.bulk.shared::cluster.global.mbarrier::complete_tx::bytes [%0], [%1], %2, [%3];"
                 :: "r"(dst), "l"(src), "r"(bytes), "r"(bar) : "memory");
}
__device__ __forceinline__ void mbar_wait(uint32_t a, uint32_t ph){
    asm volatile("{\n\t.reg .pred P;\n\tWL%=:\n\tmbarrier.try_wait.parity.shared.b64 P, [%0], %1;\n\t@P bra WD%=;\n\tbra WL%=;\n\tWD%=:\n\t}"
                 :: "r"(a), "r"(ph) : "memory");
}

// ================= k_dots: content scores (unscaled by beta), wide grid =================
// 128 blocks = 8 b x 16 chunks of 128 rows; 512 threads.
__global__ void __launch_bounds__(512)
k_dots(const float* __restrict__ mem, const float* __restrict__ controls)
{
    int b = blockIdx.x >> 4, chunk = blockIdx.x & 15;
    int n0 = chunk * 128;
    int tid = threadIdx.x, w = tid >> 5, lane = tid & 31;
    int half = lane >> 4, h = lane & 15;

    __shared__ __align__(16) float s_key[256];
    __shared__ float s_kn[4];

    if (tid < 256) s_key[tid] = controls[b*272 + tid];
    __syncthreads();
    if (w < 4) {
        float x0 = s_key[w*64 + lane], x1 = s_key[w*64 + 32 + lane];
        float q = x0*x0 + x1*x1;
        #pragma unroll
        for (int m = 16; m; m >>= 1) q += __shfl_xor_sync(~0u, q, m);
        if (lane == 0) s_kn[w] = sqrtf(q);
    }
    __syncthreads();

    #pragma unroll
    for (int it = 0; it < 4; ++it) {
        int n = n0 + w*8 + it*2 + half;
        float4 m4 = *(const float4*)(mem + ((size_t)(b*N_ + n))*W_ + h*4);
        float4 k0 = *(const float4*)(s_key + 0*64 + h*4);
        float4 k1 = *(const float4*)(s_key + 1*64 + h*4);
        float4 k2 = *(const float4*)(s_key + 2*64 + h*4);
        float4 k3 = *(const float4*)(s_key + 3*64 + h*4);
        float d0 = m4.x*k0.x + m4.y*k0.y + m4.z*k0.z + m4.w*k0.w;
        float d1 = m4.x*k1.x + m4.y*k1.y + m4.z*k1.z + m4.w*k1.w;
        float d2 = m4.x*k2.x + m4.y*k2.y + m4.z*k2.z + m4.w*k2.w;
        float d3 = m4.x*k3.x + m4.y*k3.y + m4.z*k3.z + m4.w*k3.w;
        float nr = m4.x*m4.x + m4.y*m4.y + m4.z*m4.z + m4.w*m4.w;
        u64 p01 = pk(d0, d1), p23 = pk(d2, d3);
        #pragma unroll
        for (int m = 8; m; m >>= 1) {
            p01 = add2(p01, __shfl_xor_sync(~0u, p01, m));
            p23 = add2(p23, __shfl_xor_sync(~0u, p23, m));
            nr += __shfl_xor_sync(~0u, nr, m);
        }
        if (h == 0) {
            float mns = sqrtf(nr);
            float a0, a1, a2, a3;
            upk(p01, a0, a1); upk(p23, a2, a3);
            g_cw[(b*4+0)*N_ + n] = a0/(s_kn[0]*mns + EPS_);
            g_cw[(b*4+1)*N_ + n] = a1/(s_kn[1]*mns + EPS_);
            g_cw[(b*4+2)*N_ + n] = a2/(s_kn[2]*mns + EPS_);
            g_cw[(b*4+3)*N_ + n] = a3/(s_kn[3]*mns + EPS_);
        }
    }
}

// ================= k_smax: scalars + beta-scaled softmax, one block per (b,r) =================
__global__ void __launch_bounds__(512)
k_smax(const float* __restrict__ controls, const float* __restrict__ ww,
       const float* __restrict__ p, const float* __restrict__ prw,
       float* __restrict__ out)
{
    int br = blockIdx.x, b = br >> 2, r = br & 3;
    int tid = threadIdx.x, warp = tid >> 5, lane = tid & 31;
    __shared__ u64   s_r1[16];
    __shared__ float s_r2[16];
    __shared__ float s_bk[2];

    float accP = 0.f, accS = 0.f;
    for (int k = tid; k < N_; k += 512) {
        float t = prw[br*N_ + k];
        accP += p [b*N_ + k]*t;
        accS += ww[b*N_ + k]*t;
    }
    u64 pp = pk(accP, accS);
    #pragma unroll
    for (int m = 16; m; m >>= 1) pp = add2(pp, __shfl_xor_sync(~0u, pp, m));
    if (lane == 0) s_r1[warp] = pp;
    __syncthreads();
    if (tid == 0) {
        float P = 0.f, S = 0.f;
        #pragma unroll
        for (int i = 0; i < 16; ++i) { float x, y; upk(s_r1[i], x, y); P += x; S += y; }
        g_P[br] = P; g_S[br] = S;
        float x = controls[b*272 + 256 + r];
        s_bk[0] = 1.f + ((x > 15.f) ? x : log1pf(__expf(x)));   // beta
        float e0 = controls[b*272 + 260 + r*3 + 0];
        float e1 = controls[b*272 + 260 + r*3 + 1];
        float e2 = controls[b*272 + 260 + r*3 + 2];
        float mm = fmaxf(e0, fmaxf(e1, e2));
        float x0 = __expf(e0-mm), x1 = __expf(e1-mm), x2 = __expf(e2-mm);
        float inv = 1.f/(x0+x1+x2);
        g_gate[br*3+0] = x0*inv; g_gate[br*3+1] = x1*inv; g_gate[br*3+2] = x2*inv;
    }
    if (tid < 64) out[br*64 + tid] = 0.f;
    __syncthreads();

    float beta = s_bk[0];
    float v[4]; float mx = -1e30f;
    #pragma unroll
    for (int k = 0; k < 4; ++k) { v[k] = g_cw[br*N_ + tid + k*512]*beta; mx = fmaxf(mx, v[k]); }
    #pragma unroll
    for (int m = 16; m; m >>= 1) mx = fmaxf(mx, __shfl_xor_sync(~0u, mx, m));
    if (lane == 0) s_r2[warp] = mx;
    __syncthreads();
    if (tid == 0) { float m2 = s_r2[0]; for (int i = 1; i < 16; ++i) m2 = fmaxf(m2, s_r2[i]); s_bk[1] = m2; }
    __syncthreads();
    mx = s_bk[1];
    float s = 0.f;
    #pragma unroll
    for (int k = 0; k < 4; ++k) { v[k] = __expf(v[k]-mx); s += v[k]; }
    #pragma unroll
    for (int m = 16; m; m >>= 1) s += __shfl_xor_sync(~0u, s, m);
    __syncthreads();
    if (lane == 0) s_r2[warp] = s;
    __syncthreads();
    if (tid == 0) { float t = 0.f; for (int i = 0; i < 16; ++i) t += s_r2[i]; s_bk[0] = 1.f/t; }
    __syncthreads();
    float inv = s_bk[0];
    #pragma unroll
    for (int k = 0; k < 4; ++k) g_cw[br*N_ + tid + k*512] = v[k]*inv;
}

// ================= k_stream: single pass over L with bulk-async double buffer =================
#define STAGE_BYTES 65536         // 8 rows x 2048 x 4B
#define SMEM_DYN    166416
#define SP(sel,row,w) s_part[(((sel)*128 + (row))*16) + (w)]

__global__ void __launch_bounds__(512)
k_stream(const float* __restrict__ L, const float* __restrict__ ww,
         const float* __restrict__ prw)
{
    extern __shared__ __align__(16) unsigned char dsm[];
    float* stg0   = (float*)(dsm);
    float* stg1   = (float*)(dsm + 65536);
    u64*   s_part = (u64*)  (dsm + 131072);   // [2][128][16]
    float* s_a    = (float*)(dsm + 163840);
    float* s_pi   = (float*)(dsm + 164352);   // [4][128]
    u64*   s_bar  = (u64*)  (dsm + 166400);

    int b = blockIdx.x >> 4, tile = blockIdx.x & 15, i0 = tile*TI_;
    int tid = threadIdx.x, w = tid >> 5, lane = tid & 31;
    int half = lane >> 4, h = lane & 15;

    if (tid < TI_) s_a[tid] = 1.f - ww[b*N_ + i0 + tid];
    if (tid < R_*TI_) s_pi[tid] = prw[(b*4 + (tid >> 7))*N_ + i0 + (tid & 127)];

    uint32_t bar0 = smem_u32(s_bar), bar1 = bar0 + 8;
    uint32_t st0 = smem_u32(stg0), st1 = smem_u32(stg1);
    if (tid == 0) { mbar_init(bar0, 1); mbar_init(bar1, 1); }
    __syncthreads();

    const char* src = (const char*)(L + ((size_t)(b*N_ + i0))*N_);
    if (tid == 0) {
        mbar_expect(bar0, STAGE_BYTES); bulk_g2s(st0, src,               STAGE_BYTES, bar0);
        mbar_expect(bar1, STAGE_BYTES); bulk_g2s(st1, src + STAGE_BYTES, STAGE_BYTES, bar1);
    }

    int jA = w*128 + h*4, jB = jA + 64;
    u64 pj[4][4];
    #pragma unroll
    for (int r = 0; r < 4; ++r) {
        float4 A  = *(const float4*)(prw + (b*4+r)*N_ + jA);
        float4 Bv = *(const float4*)(prw + (b*4+r)*N_ + jB);
        pj[r][0] = pk(A.x, A.y);  pj[r][1] = pk(A.z, A.w);
        pj[r][2] = pk(Bv.x, Bv.y); pj[r][3] = pk(Bv.z, Bv.w);
    }
    float4 wA = *(const float4*)(ww + b*N_ + jA);
    float4 wB = *(const float4*)(ww + b*N_ + jB);
    u64 wj[4] = { pk(wA.x,wA.y), pk(wA.z,wA.w), pk(wB.x,wB.y), pk(wB.z,wB.w) };

    u64 bw[4][4];
    #pragma unroll
    for (int r = 0; r < 4; ++r)
        #pragma unroll
        for (int k = 0; k < 4; ++k) bw[r][k] = 0ull;

    uint32_t ph0 = 0, ph1 = 0;
    for (int g = 0; g < 16; ++g) {
        if (g & 1) { mbar_wait(bar1, ph1); ph1 ^= 1; }
        else       { mbar_wait(bar0, ph0); ph0 ^= 1; }
        const float* stg = (g & 1) ? stg1 : stg0;

        #pragma unroll
        for (int it = 0; it < 4; ++it) {
            int lrow = it*2 + half;
            int row  = g*8 + lrow;
            float4 A  = *(const float4*)(stg + lrow*2048 + jA);
            float4 Bv = *(const float4*)(stg + lrow*2048 + jB);
            u64 l0 = pk(A.x,A.y), l1 = pk(A.z,A.w), l2 = pk(Bv.x,Bv.y), l3 = pk(Bv.z,Bv.w);
            float a = s_a[row];
            u64 av = pk(a, a);
            u64 c0 = mul2(sub2(av, wj[0]), l0);
            u64 c1 = mul2(sub2(av, wj[1]), l1);
            u64 c2 = mul2(sub2(av, wj[2]), l2);
            u64 c3 = mul2(sub2(av, wj[3]), l3);

            float f[4];
            #pragma unroll
            for (int r = 0; r < 4; ++r) {
                u64 t = mul2(c0, pj[r][0]);
                t = fma2(c1, pj[r][1], t);
                t = fma2(c2, pj[r][2], t);
                t = fma2(c3, pj[r][3], t);
                float x, y; upk(t, x, y); f[r] = x + y;
                float pi = s_pi[r*128 + row];
                u64 pr = pk(pi, pi);
                bw[r][0] = fma2(c0, pr, bw[r][0]);
                bw[r][1] = fma2(c1, pr, bw[r][1]);
                bw[r][2] = fma2(c2, pr, bw[r][2]);
                bw[r][3] = fma2(c3, pr, bw[r][3]);
            }
            u64 f01 = pk(f[0], f[1]), f23 = pk(f[2], f[3]);
            #pragma unroll
            for (int m = 8; m; m >>= 1) {
                f01 = add2(f01, __shfl_xor_sync(~0u, f01, m));
                f23 = add2(f23, __shfl_xor_sync(~0u, f23, m));
            }
            if (h == 0) { SP(0, row, w) = f01; SP(1, row, w) = f23; }
        }
        __syncthreads();
        if (tid == 0 && g + 2 < 16) {
            uint32_t bb = (g & 1) ? bar1 : bar0;
            uint32_t st = (g & 1) ? st1  : st0;
            mbar_expect(bb, STAGE_BYTES);
            bulk_g2s(st, src + (size_t)(g+2)*STAGE_BYTES, STAGE_BYTES, bb);
        }
    }

    // bwd: combine halves, flush per-tile partial
    #pragma unroll
    for (int r = 0; r < 4; ++r)
        #pragma unroll
        for (int k = 0; k < 4; ++k)
            bw[r][k] = add2(bw[r][k], __shfl_xor_sync(~0u, bw[r][k], 16));
    if (half == 0) {
        #pragma unroll
        for (int r = 0; r < 4; ++r) {
            float* dst = g_bwdp + ((size_t)((b*16 + tile)*4 + r))*N_;
            ulonglong2 v0; v0.x = bw[r][0]; v0.y = bw[r][1];
            ulonglong2 v1; v1.x = bw[r][2]; v1.y = bw[r][3];
            *(ulonglong2*)(dst + jA) = v0;
            *(ulonglong2*)(dst + jB) = v1;
        }
    }

    // fold fwd partials: one (row,r) per thread
    {
        int row = tid >> 2, r = tid & 3;
        const float* sp = (const float*)&SP(r >> 1, row, 0);
        float s = 0.f;
        #pragma unroll
        for (int w2 = 0; w2 < 16; ++w2) s += sp[w2*2 + (r & 1)];
        g_fwd[(b*4 + r)*N_ + i0 + row] = s;
    }
}

// ================= k_post: rw assembly + read vector =================
__global__ void __launch_bounds__(256)
k_post(const float* __restrict__ mem, const float* __restrict__ L,
       const float* __restrict__ ww, const float* __restrict__ p,
       const float* __restrict__ prw, float* __restrict__ out)
{
    int b = blockIdx.x >> 3, c = blockIdx.x & 7;
    int n0 = c*256;
    int tid = threadIdx.x, warp = tid >> 5, lane = tid & 31;
    __shared__ float s_rw[4][256];
    __shared__ float s_acc[8][4][64];

    int n = n0 + tid;
    float wn  = ww[b*N_ + n];
    float pn  = p [b*N_ + n];
    float Lnn = L[((size_t)(b*N_ + n))*N_ + n];
    float ell = (1.f - 2.f*wn)*Lnn + wn*pn;
    #pragma unroll
    for (int r = 0; r < 4; ++r) {
        int br = b*4 + r;
        float bp = 0.f;
        #pragma unroll
        for (int t = 0; t < 16; ++t) bp += g_bwdp[((size_t)((b*16 + t)*4 + r))*N_ + n];
        float prn = prw[br*N_ + n];
        float fwd = g_fwd[br*N_ + n] + wn*g_P[br] - ell*prn;
        float bwd = bp + pn*g_S[br] - ell*prn;
        s_rw[r][tid] = g_gate[br*3]*fwd + g_gate[br*3+1]*bwd + g_gate[br*3+2]*g_cw[br*N_ + n];
    }
    __syncthreads();

    float2 acc[4];
    #pragma unroll
    for (int r = 0; r < 4; ++r) { acc[r].x = 0.f; acc[r].y = 0.f; }
    for (int k = 0; k < 32; ++k) {
        int nl = warp*32 + k;
        float2 m = *(const float2*)(mem + ((size_t)(b*N_ + n0 + nl))*W_ + lane*2);
        #pragma unroll
        for (int r = 0; r < 4; ++r) {
            float rv = s_rw[r][nl];
            acc[r].x += m.x*rv;
            acc[r].y += m.y*rv;
        }
    }
    #pragma unroll
    for (int r = 0; r < 4; ++r) {
        s_acc[warp][r][lane*2]   = acc[r].x;
        s_acc[warp][r][lane*2+1] = acc[r].y;
    }
    __syncthreads();
    {
        int r = tid >> 6, wd = tid & 63;
        float s = 0.f;
        #pragma unroll
        for (int k = 0; k < 8; ++k) s += s_acc[k][r][wd];
        atomicAdd(&out[(b*4 + r)*64 + wd], s);
    }
}

// ================= launcher =================
extern "C" void kernel_launch(void* const* d_in, const int* in_sizes, int n_in,
                              void* d_out, int out_size)
{
    const float* mem      = (const float*)d_in[0];
    const float* controls = (const float*)d_in[1];
    const float* ww       = (const float*)d_in[2];
    const float* L        = (const float*)d_in[3];
    const float* p        = (const float*)d_in[4];
    const float* prw      = (const float*)d_in[5];
    float* out = (float*)d_out;

    cudaFuncSetAttribute(k_stream, cudaFuncAttributeMaxDynamicSharedMemorySize, SMEM_DYN);

    k_dots  <<<B_*16, 512>>>(mem, controls);
    k_smax  <<<B_*R_, 512>>>(controls, ww, p, prw, out);
    k_stream<<<B_*16, 512, SMEM_DYN>>>(L, ww, prw);
    k_post  <<<B_*8, 256>>>(mem, L, ww, p, prw, out);
}